// round 1
// baseline (speedup 1.0000x reference)
#include <cuda_runtime.h>

// Problem constants
#define NPIX   16384            // B*H*W = 16*32*32
#define NCODE  1024             // N
#define DDIM   256              // D
#define ZQ_SIZE 4194304         // B*D*H*W
#define KL_OFF  ZQ_SIZE
#define IDX_OFF (ZQ_SIZE + 1)
#define PERP_OFF (ZQ_SIZE + 1 + NPIX)

// Scratch (static device arrays — no allocation)
__device__ float g_sample[(size_t)NPIX * NCODE];   // 64 MB, [pixel][n]
__device__ float g_avg[NCODE];
__device__ float g_kl;

// Fused lgamma + digamma: shift x up to >= 6, then Stirling / asymptotic series.
__device__ __forceinline__ void lgamma_digamma(float x, float& lg, float& ps) {
    float prod = 1.f, rs = 0.f;
    #pragma unroll 1
    while (x < 6.f) {
        prod *= x;
        rs += __fdividef(1.f, x);
        x += 1.f;
    }
    float lx   = __logf(x);
    float inv  = __fdividef(1.f, x);
    float inv2 = inv * inv;
    // lnGamma(x) ~ (x-1/2)ln x - x + 0.5 ln(2pi) + 1/(12x) - 1/(360x^3) + 1/(1260x^5)
    lg = (x - 0.5f) * lx - x + 0.9189385332046727f
       + inv * (0.083333333333f - inv2 * (2.7777777778e-3f - inv2 * 7.9365079365e-4f));
    lg -= __logf(prod);
    // psi(x) ~ ln x - 1/(2x) - 1/(12x^2) + 1/(120x^4) - 1/(252x^6)
    ps = lx - 0.5f * inv
       - inv2 * (0.083333333333f - inv2 * (8.3333333333e-3f - inv2 * 3.9682539683e-3f))
       - rs;
}

__global__ void init_kernel() {
    int t = threadIdx.x;
    if (t < NCODE) g_avg[t] = 0.f;
    if (t == 0) g_kl = 0.f;
}

// One block per (b, h) row of 32 pixels. 512 threads.
// Phase A: coalesced load of logits, softplus+1, transpose to smem [w][n].
// Phase B: each warp handles 2 pixels; per-pixel reductions over n.
extern __shared__ float smem_dyn[];
__global__ __launch_bounds__(512) void pixel_kernel(
    const float* __restrict__ logits,
    const float* __restrict__ noise,
    float* __restrict__ out)
{
    float* alpha_t = smem_dyn;              // [32][1025]  (padded)
    float* avg_loc = smem_dyn + 32 * 1025;  // [1024]
    const int tid = threadIdx.x;
    const int blk = blockIdx.x;             // b*32 + h
    const int b = blk >> 5, h = blk & 31;

    for (int i = tid; i < NCODE; i += 512) avg_loc[i] = 0.f;

    // Phase A: logits[((b*1024+n)*32+h)*32 + w]
    const float* lg = logits + (size_t)b * NCODE * 1024 + (size_t)h * 32;
    #pragma unroll 4
    for (int i = tid; i < 32 * NCODE; i += 512) {
        int n = i >> 5, w = i & 31;
        float x = lg[(size_t)n * 1024 + w];
        float sp = fmaxf(x, 0.f) + log1pf(__expf(-fabsf(x)));  // softplus
        alpha_t[w * 1025 + n] = sp + 1.f;
    }
    __syncthreads();

    const int warp = tid >> 5, lane = tid & 31;
    for (int pw = 0; pw < 2; pw++) {
        const int w = warp * 2 + pw;
        const int p = blk * 32 + w;
        float* row = alpha_t + w * 1025;
        const float* nz = noise + (size_t)p * NCODE;

        // Pass 1: sums for KL + gumbel logits y, max/argmax
        float S = 0.f, slg = 0.f, sdg = 0.f, m = -1e30f;
        int bi = 0;
        #pragma unroll 2
        for (int k = 0; k < 32; k++) {
            int n = k * 32 + lane;
            float a = row[n];
            float lga, psa;
            lgamma_digamma(a, lga, psa);
            S += a;
            slg += lga;
            sdg += (a - 1.f) * psa;
            float u = nz[n];
            float gmb = -__logf(-__logf(u));
            float y = 2.f * (__logf(a) + gmb);   // 1/TEMP = 2; log S cancels in softmax
            row[n] = y;
            if (y > m) { m = y; bi = n; }
        }
        #pragma unroll
        for (int o = 16; o; o >>= 1) {
            S   += __shfl_xor_sync(0xffffffffu, S, o);
            slg += __shfl_xor_sync(0xffffffffu, slg, o);
            sdg += __shfl_xor_sync(0xffffffffu, sdg, o);
            float mo = __shfl_xor_sync(0xffffffffu, m, o);
            int   bo = __shfl_xor_sync(0xffffffffu, bi, o);
            if (mo > m || (mo == m && bo < bi)) { m = mo; bi = bo; }
        }

        // Pass 2: exp + normalizer
        float Z = 0.f;
        #pragma unroll 4
        for (int k = 0; k < 32; k++) {
            int n = k * 32 + lane;
            float e = __expf(row[n] - m);
            row[n] = e;
            Z += e;
        }
        #pragma unroll
        for (int o = 16; o; o >>= 1) Z += __shfl_xor_sync(0xffffffffu, Z, o);
        float invZ = __fdividef(1.f, Z);

        // Pass 3: write sample, accumulate avg_probs locally
        float* srow = g_sample + (size_t)p * NCODE;
        #pragma unroll 4
        for (int k = 0; k < 32; k++) {
            int n = k * 32 + lane;
            float s = row[n] * invZ;
            srow[n] = s;
            atomicAdd(&avg_loc[n], s);
        }

        if (lane == 0) {
            float lgS, psS, lgN, psN;
            lgamma_digamma(S, lgS, psS);
            lgamma_digamma(1024.f, lgN, psN);
            float kl = lgS - slg - lgN + sdg - (S - 1024.f) * psS;
            atomicAdd(&g_kl, kl);
            out[IDX_OFF + p] = (float)bi;
        }
    }
    __syncthreads();
    for (int i = tid; i < NCODE; i += 512)
        atomicAdd(&g_avg[i], avg_loc[i]);
}

// z_q GEMM: C[d][p] = sum_n codebook[n][d] * sample[p][n]
// M=256 (d), N=16384 (p), K=1024 (n). 64x64x16 tile, 256 threads, 4x4/thread.
#define GBM 64
#define GBN 64
#define GBK 16
__global__ __launch_bounds__(256) void gemm_kernel(
    const float* __restrict__ cb,   // [1024][256]
    float* __restrict__ out)        // z_q at offset 0: [B][D][H*W]
{
    __shared__ float As[GBK][GBM];      // [k][d]
    __shared__ float Bs[GBK][GBN + 4];  // [k][p]
    const int tid = threadIdx.x;
    const int p0 = blockIdx.x * GBN;
    const int d0 = blockIdx.y * GBM;
    const int tx = tid & 15, ty = tid >> 4;

    const int arow = tid >> 4;          // k (0..15)
    const int acol = (tid & 15) * 4;    // d
    const int brow = tid >> 2;          // p (0..63)
    const int bcol = (tid & 3) * 4;     // k

    float acc[4][4] = {};
    const float* sp = g_sample + (size_t)p0 * NCODE;

    for (int k0 = 0; k0 < NCODE; k0 += GBK) {
        float4 av = *(const float4*)&cb[(size_t)(k0 + arow) * DDIM + d0 + acol];
        float4 bv = *(const float4*)&sp[(size_t)brow * NCODE + k0 + bcol];
        __syncthreads();
        *(float4*)&As[arow][acol] = av;
        Bs[bcol + 0][brow] = bv.x;
        Bs[bcol + 1][brow] = bv.y;
        Bs[bcol + 2][brow] = bv.z;
        Bs[bcol + 3][brow] = bv.w;
        __syncthreads();
        #pragma unroll
        for (int kk = 0; kk < GBK; kk++) {
            float4 ra = *(const float4*)&As[kk][ty << 2];
            float4 rb = *(const float4*)&Bs[kk][tx << 2];
            float a4[4] = {ra.x, ra.y, ra.z, ra.w};
            float b4[4] = {rb.x, rb.y, rb.z, rb.w};
            #pragma unroll
            for (int i = 0; i < 4; i++)
                #pragma unroll
                for (int j = 0; j < 4; j++)
                    acc[i][j] += a4[i] * b4[j];
        }
    }

    const int b = p0 >> 10;
    const int hw = (p0 & 1023) + tx * 4;
    #pragma unroll
    for (int i = 0; i < 4; i++) {
        int d = d0 + ty * 4 + i;
        float4 v = make_float4(acc[i][0], acc[i][1], acc[i][2], acc[i][3]);
        *(float4*)&out[(size_t)b * (DDIM * 1024) + (size_t)d * 1024 + hw] = v;
    }
}

__global__ void finalize_kernel(float* __restrict__ out) {
    __shared__ float red[32];
    int t = threadIdx.x;   // 1024 threads
    float v = g_avg[t] * (1.f / 16384.f);
    float hterm = v * __logf(v + 1e-10f);
    #pragma unroll
    for (int o = 16; o; o >>= 1) hterm += __shfl_xor_sync(0xffffffffu, hterm, o);
    if ((t & 31) == 0) red[t >> 5] = hterm;
    __syncthreads();
    if (t < 32) {
        float s = red[t];
        #pragma unroll
        for (int o = 16; o; o >>= 1) s += __shfl_xor_sync(0xffffffffu, s, o);
        if (t == 0) {
            out[PERP_OFF] = __expf(-s);
            out[KL_OFF] = (1e-3f / 16384.f) * g_kl;
        }
    }
}

extern "C" void kernel_launch(void* const* d_in, const int* in_sizes, int n_in,
                              void* d_out, int out_size) {
    const float* logits = (const float*)d_in[0];
    const float* cb     = (const float*)d_in[1];
    const float* noise  = (const float*)d_in[2];
    float* out = (float*)d_out;

    const int smem_bytes = (32 * 1025 + NCODE) * 4;   // 135296
    cudaFuncSetAttribute(pixel_kernel,
                         cudaFuncAttributeMaxDynamicSharedMemorySize, smem_bytes);

    init_kernel<<<1, 1024>>>();
    pixel_kernel<<<512, 512, smem_bytes>>>(logits, noise, out);
    gemm_kernel<<<dim3(NPIX / GBN, DDIM / GBM), 256>>>(cb, out);
    finalize_kernel<<<1, 1024>>>(out);
}

// round 3
// speedup vs baseline: 1.3255x; 1.3255x over previous
#include <cuda_runtime.h>
#include <cstdint>

// Problem constants
#define NPIX   16384            // B*H*W
#define NCODE  1024             // N (= K of the GEMM)
#define DDIM   256              // D (= M of the GEMM)
#define ZQ_SIZE 4194304         // B*D*H*W
#define KL_OFF  ZQ_SIZE
#define IDX_OFF (ZQ_SIZE + 1)
#define PERP_OFF (ZQ_SIZE + 1 + NPIX)

// Static device scratch (no allocation allowed)
__device__ float g_sample[(size_t)NPIX * NCODE];   // 64 MB, [pixel][k], tf32-rounded
__device__ float g_cbR[(size_t)NCODE * DDIM];      // 1 MB,  [k][d],   tf32-rounded
__device__ float g_avg[NCODE];
__device__ float g_kl;

// ---------------------------------------------------------------- helpers
__device__ __forceinline__ float rna_tf32(float x) {
    uint32_t r; asm("cvt.rna.tf32.f32 %0, %1;" : "=r"(r) : "f"(x));
    return __uint_as_float(r);
}
__device__ __forceinline__ uint32_t smem_u32(const void* p) {
    uint32_t a;
    asm("{ .reg .u64 t; cvta.to.shared.u64 t, %1; cvt.u32.u64 %0, t; }" : "=r"(a) : "l"(p));
    return a;
}
__device__ __forceinline__ void cpa16(uint32_t d, const float* s) {
    asm volatile("cp.async.cg.shared.global [%0], [%1], 16;" :: "r"(d), "l"(s));
}
__device__ __forceinline__ void mma_tf32(float* c, const uint32_t* a, const uint32_t* b) {
    asm volatile(
        "mma.sync.aligned.m16n8k8.row.col.f32.tf32.tf32.f32 "
        "{%0,%1,%2,%3}, {%4,%5,%6,%7}, {%8,%9}, {%0,%1,%2,%3};"
        : "+f"(c[0]), "+f"(c[1]), "+f"(c[2]), "+f"(c[3])
        : "r"(a[0]), "r"(a[1]), "r"(a[2]), "r"(a[3]), "r"(b[0]), "r"(b[1]));
}

// ---------------------------------------------------------------- init
__global__ void init_kernel() {
    int t = threadIdx.x;
    if (t < NCODE) g_avg[t] = 0.f;
    if (t == 0) g_kl = 0.f;
}

// round codebook to tf32 once (layout unchanged: [n=k][d])
__global__ __launch_bounds__(1024) void round_cb(const float* __restrict__ cb) {
    int i = blockIdx.x * 1024 + threadIdx.x;
    g_cbR[i] = rna_tf32(cb[i]);
}

// ---------------------------------------------------------------- fused lgamma + digamma
__device__ __forceinline__ void lgamma_digamma(float x, float& lg, float& ps) {
    float prod = 1.f, rs = 0.f;
    #pragma unroll 1
    while (x < 6.f) {
        prod *= x;
        rs += __fdividef(1.f, x);
        x += 1.f;
    }
    float lx   = __logf(x);
    float inv  = __fdividef(1.f, x);
    float inv2 = inv * inv;
    lg = (x - 0.5f) * lx - x + 0.9189385332046727f
       + inv * (0.083333333333f - inv2 * (2.7777777778e-3f - inv2 * 7.9365079365e-4f));
    lg -= __logf(prod);
    ps = lx - 0.5f * inv
       - inv2 * (0.083333333333f - inv2 * (8.3333333333e-3f - inv2 * 3.9682539683e-3f))
       - rs;
}

// ---------------------------------------------------------------- per-pixel pass
extern __shared__ float smem_dyn[];
__global__ __launch_bounds__(512) void pixel_kernel(
    const float* __restrict__ logits,
    const float* __restrict__ noise,
    float* __restrict__ out)
{
    float* alpha_t = smem_dyn;              // [32][1025]
    float* avg_loc = smem_dyn + 32 * 1025;  // [1024]
    const int tid = threadIdx.x;
    const int blk = blockIdx.x;             // b*32 + h
    const int b = blk >> 5, h = blk & 31;

    for (int i = tid; i < NCODE; i += 512) avg_loc[i] = 0.f;

    const float* lg = logits + (size_t)b * NCODE * 1024 + (size_t)h * 32;
    #pragma unroll 4
    for (int i = tid; i < 32 * NCODE; i += 512) {
        int n = i >> 5, w = i & 31;
        float x = lg[(size_t)n * 1024 + w];
        float sp = fmaxf(x, 0.f) + log1pf(__expf(-fabsf(x)));
        alpha_t[w * 1025 + n] = sp + 1.f;
    }
    __syncthreads();

    const int warp = tid >> 5, lane = tid & 31;
    for (int pw = 0; pw < 2; pw++) {
        const int w = warp * 2 + pw;
        const int p = blk * 32 + w;
        float* row = alpha_t + w * 1025;
        const float* nz = noise + (size_t)p * NCODE;

        float S = 0.f, slg = 0.f, sdg = 0.f, m = -1e30f;
        int bi = 0;
        #pragma unroll 2
        for (int k = 0; k < 32; k++) {
            int n = k * 32 + lane;
            float a = row[n];
            float lga, psa;
            lgamma_digamma(a, lga, psa);
            S += a;
            slg += lga;
            sdg += (a - 1.f) * psa;
            float u = nz[n];
            float gmb = -__logf(-__logf(u));
            float y = 2.f * (__logf(a) + gmb);   // 1/TEMP = 2; log S cancels
            row[n] = y;
            if (y > m) { m = y; bi = n; }
        }
        #pragma unroll
        for (int o = 16; o; o >>= 1) {
            S   += __shfl_xor_sync(0xffffffffu, S, o);
            slg += __shfl_xor_sync(0xffffffffu, slg, o);
            sdg += __shfl_xor_sync(0xffffffffu, sdg, o);
            float mo = __shfl_xor_sync(0xffffffffu, m, o);
            int   bo = __shfl_xor_sync(0xffffffffu, bi, o);
            if (mo > m || (mo == m && bo < bi)) { m = mo; bi = bo; }
        }

        float Z = 0.f;
        #pragma unroll 4
        for (int k = 0; k < 32; k++) {
            int n = k * 32 + lane;
            float e = __expf(row[n] - m);
            row[n] = e;
            Z += e;
        }
        #pragma unroll
        for (int o = 16; o; o >>= 1) Z += __shfl_xor_sync(0xffffffffu, Z, o);
        float invZ = __fdividef(1.f, Z);

        float* srow = g_sample + (size_t)p * NCODE;
        #pragma unroll 4
        for (int k = 0; k < 32; k++) {
            int n = k * 32 + lane;
            float s = row[n] * invZ;
            srow[n] = rna_tf32(s);           // tf32-ready for the MMA
            atomicAdd(&avg_loc[n], s);
        }

        if (lane == 0) {
            float lgS, psS, lgN, psN;
            lgamma_digamma(S, lgS, psS);
            lgamma_digamma(1024.f, lgN, psN);
            float kl = lgS - slg - lgN + sdg - (S - 1024.f) * psS;
            atomicAdd(&g_kl, kl);
            out[IDX_OFF + p] = (float)bi;
        }
    }
    __syncthreads();
    for (int i = tid; i < NCODE; i += 512)
        atomicAdd(&g_avg[i], avg_loc[i]);
}

// ---------------------------------------------------------------- tf32 mma.sync GEMM
// C[d=256][p=128-tile] = sum_k cb[k][d] * sample[p][k]
// Block: 256 threads (8 warps), warp tile 64x64 (warp_m = warp&3, warp_n = warp>>2).
// As[k][d] stride 264 floats, Bs[k][p] stride 136 floats (both mod32==8 -> conflict-free
// fragment gathers: bank = tig*8 + gid + const).
#define SA 264
#define SB 136
#define GEMM_SMEM ((2 * 16 * SA + 2 * 16 * SB) * 4)   // 51200 B

__global__ __launch_bounds__(256, 1) void gemm_mma(float* __restrict__ out) {
    extern __shared__ float sm[];
    float* Asm[2] = { sm, sm + 16 * SA };
    float* Bsm[2] = { sm + 32 * SA, sm + 32 * SA + 16 * SB };

    const int tid = threadIdx.x, warp = tid >> 5, lane = tid & 31;
    const int gid = lane >> 2, tig = lane & 3;
    const int wm = warp & 3, wn = warp >> 2;       // m-offset 64*wm, n-offset 64*wn
    const int p0 = blockIdx.x * 128;

    const float* spl = g_sample + (size_t)p0 * NCODE;

    // B register staging: thread t handles p_local = t&127, k-half j = t>>7 (8 k each)
    const int pl = tid & 127, j = tid >> 7;
    const float* bsrc = spl + (size_t)pl * NCODE + j * 8;
    float4 br0 = *(const float4*)(bsrc);
    float4 br1 = *(const float4*)(bsrc + 4);

    // A cp.async issue: 16 k-rows x 256 d, 16B chunks
    const uint32_t a_s0 = smem_u32(Asm[0]), a_s1 = smem_u32(Asm[1]);
    #pragma unroll
    for (int i = 0; i < 4; i++) {
        int idx = tid + i * 256, row = idx >> 6, col = (idx & 63) * 4;
        cpa16(a_s0 + (row * SA + col) * 4, g_cbR + row * DDIM + col);
    }
    asm volatile("cp.async.commit_group;" ::: "memory");

    float acc[4][8][4] = {};

    for (int c = 0; c < 64; c++) {
        const int buf = c & 1;
        asm volatile("cp.async.wait_group 0;" ::: "memory");

        // STS staged B (transpose into [k][p])
        float* bs = Bsm[buf];
        bs[(j * 8 + 0) * SB + pl] = br0.x;
        bs[(j * 8 + 1) * SB + pl] = br0.y;
        bs[(j * 8 + 2) * SB + pl] = br0.z;
        bs[(j * 8 + 3) * SB + pl] = br0.w;
        bs[(j * 8 + 4) * SB + pl] = br1.x;
        bs[(j * 8 + 5) * SB + pl] = br1.y;
        bs[(j * 8 + 6) * SB + pl] = br1.z;
        bs[(j * 8 + 7) * SB + pl] = br1.w;
        __syncthreads();

        if (c < 63) {
            // next A tile
            const float* abase = g_cbR + (size_t)(c + 1) * 16 * DDIM;
            uint32_t adst = buf ? a_s0 : a_s1;
            #pragma unroll
            for (int i = 0; i < 4; i++) {
                int idx = tid + i * 256, row = idx >> 6, col = (idx & 63) * 4;
                cpa16(adst + (row * SA + col) * 4, abase + row * DDIM + col);
            }
            asm volatile("cp.async.commit_group;" ::: "memory");
            // next B regs
            const float* bn = spl + (size_t)pl * NCODE + (c + 1) * 16 + j * 8;
            br0 = *(const float4*)(bn);
            br1 = *(const float4*)(bn + 4);
        }

        // compute on buf
        const float* as = Asm[buf];
        #pragma unroll
        for (int kk = 0; kk < 16; kk += 8) {
            uint32_t afr[4][4], bfr[8][2];
            #pragma unroll
            for (int mf = 0; mf < 4; mf++) {
                int m = wm * 64 + mf * 16 + gid;
                afr[mf][0] = __float_as_uint(as[(kk + tig) * SA + m]);
                afr[mf][1] = __float_as_uint(as[(kk + tig) * SA + m + 8]);
                afr[mf][2] = __float_as_uint(as[(kk + 4 + tig) * SA + m]);
                afr[mf][3] = __float_as_uint(as[(kk + 4 + tig) * SA + m + 8]);
            }
            #pragma unroll
            for (int nf = 0; nf < 8; nf++) {
                int n = wn * 64 + nf * 8 + gid;
                bfr[nf][0] = __float_as_uint(bs[(kk + tig) * SB + n]);
                bfr[nf][1] = __float_as_uint(bs[(kk + 4 + tig) * SB + n]);
            }
            #pragma unroll
            for (int mf = 0; mf < 4; mf++)
                #pragma unroll
                for (int nf = 0; nf < 8; nf++)
                    mma_tf32(acc[mf][nf], afr[mf], bfr[nf]);
        }
        __syncthreads();
    }

    // Epilogue: c0/c1 at (gid, 2*tig..+1), c2/c3 at (gid+8, 2*tig..+1)
    const int bimg = p0 >> 10, hwb = p0 & 1023;
    #pragma unroll
    for (int mf = 0; mf < 4; mf++) {
        const int d = wm * 64 + mf * 16 + gid;
        float* orow = out + (size_t)bimg * (DDIM * 1024) + (size_t)d * 1024 + hwb;
        #pragma unroll
        for (int nf = 0; nf < 8; nf++) {
            const int col = wn * 64 + nf * 8 + 2 * tig;
            *(float2*)&orow[col]            = make_float2(acc[mf][nf][0], acc[mf][nf][1]);
            *(float2*)&orow[col + 8 * 1024] = make_float2(acc[mf][nf][2], acc[mf][nf][3]);
        }
    }
}

// ---------------------------------------------------------------- finalize
__global__ void finalize_kernel(float* __restrict__ out) {
    __shared__ float red[32];
    int t = threadIdx.x;   // 1024 threads
    float v = g_avg[t] * (1.f / 16384.f);
    float hterm = v * __logf(v + 1e-10f);
    #pragma unroll
    for (int o = 16; o; o >>= 1) hterm += __shfl_xor_sync(0xffffffffu, hterm, o);
    if ((t & 31) == 0) red[t >> 5] = hterm;
    __syncthreads();
    if (t < 32) {
        float s = red[t];
        #pragma unroll
        for (int o = 16; o; o >>= 1) s += __shfl_xor_sync(0xffffffffu, s, o);
        if (t == 0) {
            out[PERP_OFF] = __expf(-s);
            out[KL_OFF] = (1e-3f / 16384.f) * g_kl;
        }
    }
}

// ---------------------------------------------------------------- launch
extern "C" void kernel_launch(void* const* d_in, const int* in_sizes, int n_in,
                              void* d_out, int out_size) {
    const float* logits = (const float*)d_in[0];
    const float* cb     = (const float*)d_in[1];
    const float* noise  = (const float*)d_in[2];
    float* out = (float*)d_out;

    const int px_smem = (32 * 1025 + NCODE) * 4;
    cudaFuncSetAttribute(pixel_kernel,
                         cudaFuncAttributeMaxDynamicSharedMemorySize, px_smem);
    cudaFuncSetAttribute(gemm_mma,
                         cudaFuncAttributeMaxDynamicSharedMemorySize, GEMM_SMEM);

    init_kernel<<<1, 1024>>>();
    round_cb<<<256, 1024>>>(cb);
    pixel_kernel<<<512, 512, px_smem>>>(logits, noise, out);
    gemm_mma<<<NPIX / 128, 256, GEMM_SMEM>>>(out);
    finalize_kernel<<<1, 1024>>>(out);
}

// round 4
// speedup vs baseline: 2.6919x; 2.0308x over previous
#include <cuda_runtime.h>
#include <cstdint>

// Problem constants
#define NPIX   16384            // B*H*W
#define NCODE  1024             // N (= K of the GEMM)
#define DDIM   256              // D (= M of the GEMM)
#define ZQ_SIZE 4194304         // B*D*H*W
#define KL_OFF  ZQ_SIZE
#define IDX_OFF (ZQ_SIZE + 1)
#define PERP_OFF (ZQ_SIZE + 1 + NPIX)

// Static device scratch (no allocation allowed)
__device__ float g_sample[(size_t)NPIX * NCODE];   // 64 MB, [pixel][k], tf32-rounded
__device__ float g_cbR[(size_t)NCODE * DDIM];      // 1 MB,  [k][d],   tf32-rounded
__device__ float g_avg[NCODE];
__device__ float g_kl;

// ---------------------------------------------------------------- helpers
__device__ __forceinline__ float rna_tf32(float x) {
    uint32_t r; asm("cvt.rna.tf32.f32 %0, %1;" : "=r"(r) : "f"(x));
    return __uint_as_float(r);
}
__device__ __forceinline__ uint32_t smem_u32(const void* p) {
    uint32_t a;
    asm("{ .reg .u64 t; cvta.to.shared.u64 t, %1; cvt.u32.u64 %0, t; }" : "=r"(a) : "l"(p));
    return a;
}
__device__ __forceinline__ void cpa16(uint32_t d, const float* s) {
    asm volatile("cp.async.cg.shared.global [%0], [%1], 16;" :: "r"(d), "l"(s));
}
__device__ __forceinline__ void mma_tf32(float* c, const uint32_t* a, const uint32_t* b) {
    asm volatile(
        "mma.sync.aligned.m16n8k8.row.col.f32.tf32.tf32.f32 "
        "{%0,%1,%2,%3}, {%4,%5,%6,%7}, {%8,%9}, {%0,%1,%2,%3};"
        : "+f"(c[0]), "+f"(c[1]), "+f"(c[2]), "+f"(c[3])
        : "r"(a[0]), "r"(a[1]), "r"(a[2]), "r"(a[3]), "r"(b[0]), "r"(b[1]));
}

// Branch-free fused lgamma + digamma for x >= 1 (double shift + Stirling at x+2).
__device__ __forceinline__ void lgamma_digamma(float x, float& lg, float& ps) {
    float prod = x * (x + 1.f);
    float invp = __fdividef(1.f, prod);
    float x2   = x + 2.f;
    float lx   = __logf(x2);
    float inv  = __fdividef(1.f, x2);
    float inv2 = inv * inv;
    lg = (x2 - 0.5f) * lx - x2 + 0.9189385332046727f
       + inv * (0.083333333333f - inv2 * (2.7777777778e-3f - inv2 * 7.9365079365e-4f))
       - __logf(prod);
    ps = lx - 0.5f * inv
       - inv2 * (0.083333333333f - inv2 * (8.3333333333e-3f - inv2 * 3.9682539683e-3f))
       - (2.f * x + 1.f) * invp;
}

// ---------------------------------------------------------------- init
__global__ void init_kernel() {
    int t = threadIdx.x;
    if (t < NCODE) g_avg[t] = 0.f;
    if (t == 0) g_kl = 0.f;
}

// round codebook to tf32 once (layout unchanged: [n=k][d])
__global__ __launch_bounds__(1024) void round_cb(const float* __restrict__ cb) {
    int i = blockIdx.x * 1024 + threadIdx.x;
    g_cbR[i] = rna_tf32(cb[i]);
}

// ---------------------------------------------------------------- per-pixel pass
// 1024 blocks x 512 threads. Block = 16 pixels (fixed b,h; half of w-row).
// smem 65.6KB -> 2 CTAs/SM. t = alpha/(-log u); softmax == t^2 / sum t^2.
#define PXS 1025
extern __shared__ float smem_dyn[];
__global__ __launch_bounds__(512) void pixel_kernel(
    const float* __restrict__ logits,
    const float* __restrict__ noise,
    float* __restrict__ out)
{
    float* alpha_t = smem_dyn;              // [16][PXS]
    __shared__ float klsum;
    const int tid = threadIdx.x;
    const int blk = blockIdx.x;             // b*64 + h*2 + half
    const int b = blk >> 6, h = (blk >> 1) & 31, half = blk & 1;
    const int w0 = half * 16;
    if (tid == 0) klsum = 0.f;

    // Stage: softplus(logits)+1, transposed to [w][n]
    const float* lg = logits + (size_t)b * (NCODE * 1024) + (size_t)h * 32 + w0;
    #pragma unroll 4
    for (int i = tid; i < 16 * NCODE; i += 512) {
        int n = i >> 4, w = i & 15;
        float x = lg[(size_t)n * 1024 + w];
        float e = __expf(-fabsf(x));
        float sp = fmaxf(x, 0.f) + __logf(1.f + e);
        alpha_t[w * PXS + n] = sp + 1.f;
    }
    __syncthreads();

    const int warp = tid >> 5, lane = tid & 31;      // warp = pixel-in-block
    const int p = b * 1024 + h * 32 + w0 + warp;     // global pixel index
    float* row = alpha_t + warp * PXS;
    const float* nz = noise + (size_t)p * NCODE;

    // Pass 1: KL sums, t = a / (-log u), Z = sum t^2, argmax t
    float S = 0.f, slg = 0.f, sdg = 0.f, Z = 0.f, m = -1.f;
    int bi = 0;
    #pragma unroll 4
    for (int k = 0; k < 32; k++) {
        int n = k * 32 + lane;
        float a = row[n];
        float lga, psa;
        lgamma_digamma(a, lga, psa);
        S += a; slg += lga; sdg += (a - 1.f) * psa;
        float L = -__logf(nz[n]);
        float t = __fdividef(a, L);
        row[n] = t;
        Z += t * t;
        if (t > m) { m = t; bi = n; }
    }
    #pragma unroll
    for (int o = 16; o; o >>= 1) {
        S   += __shfl_xor_sync(0xffffffffu, S, o);
        slg += __shfl_xor_sync(0xffffffffu, slg, o);
        sdg += __shfl_xor_sync(0xffffffffu, sdg, o);
        Z   += __shfl_xor_sync(0xffffffffu, Z, o);
        float mo = __shfl_xor_sync(0xffffffffu, m, o);
        int   bo = __shfl_xor_sync(0xffffffffu, bi, o);
        if (mo > m || (mo == m && bo < bi)) { m = mo; bi = bo; }
    }
    float invZ = __fdividef(1.f, Z);

    // Pass 2: write normalized tf32 sample
    float* srow = g_sample + (size_t)p * NCODE;
    #pragma unroll 4
    for (int k = 0; k < 32; k++) {
        int n = k * 32 + lane;
        float t = row[n];
        srow[n] = rna_tf32(t * t * invZ);
    }

    if (lane == 0) {
        float lgS, psS, lgN, psN;
        lgamma_digamma(S, lgS, psS);
        lgamma_digamma(1024.f, lgN, psN);
        float kl = lgS - slg - lgN + sdg - (S - 1024.f) * psS;
        atomicAdd(&klsum, kl);
        out[IDX_OFF + p] = (float)bi;
    }
    __syncthreads();
    if (tid == 0) atomicAdd(&g_kl, klsum);
}

// ---------------------------------------------------------------- avg_probs column sums
// 128 blocks x 256 threads; block sums 128 rows of g_sample.
__global__ __launch_bounds__(256) void avg_kernel() {
    const int r0 = blockIdx.x * 128;
    const float* sp = g_sample + (size_t)r0 * NCODE + threadIdx.x * 4;
    float4 acc = make_float4(0.f, 0.f, 0.f, 0.f);
    #pragma unroll 4
    for (int r = 0; r < 128; r++) {
        float4 v = *(const float4*)(sp + (size_t)r * NCODE);
        acc.x += v.x; acc.y += v.y; acc.z += v.z; acc.w += v.w;
    }
    int n = threadIdx.x * 4;
    atomicAdd(&g_avg[n + 0], acc.x);
    atomicAdd(&g_avg[n + 1], acc.y);
    atomicAdd(&g_avg[n + 2], acc.z);
    atomicAdd(&g_avg[n + 3], acc.w);
}

// ---------------------------------------------------------------- tf32 mma.sync GEMM
// C[d=256][p=64-tile] = sum_k cb[k][d] * sample[p][k]
// 256 threads (8 warps), warp tile 64x32 (wm=warp&3, wn=warp>>2), 2 CTAs/SM.
#define SA 264
#define SB 72
#define GEMM_SMEM ((2 * 16 * SA + 2 * 16 * SB) * 4)   // 43008 B

__global__ __launch_bounds__(256, 2) void gemm_mma(float* __restrict__ out) {
    extern __shared__ float sm[];
    float* Asm[2] = { sm, sm + 16 * SA };
    float* Bsm[2] = { sm + 32 * SA, sm + 32 * SA + 16 * SB };

    const int tid = threadIdx.x, warp = tid >> 5, lane = tid & 31;
    const int gid = lane >> 2, tig = lane & 3;
    const int wm = warp & 3, wn = warp >> 2;       // m-offset 64*wm, n-offset 32*wn
    const int p0 = blockIdx.x * 64;

    const float* spl = g_sample + (size_t)p0 * NCODE;

    // B register staging: thread handles pixel pl, 4 k-values (j quarter)
    const int pl = tid & 63, j = tid >> 6;
    float4 br = *(const float4*)(spl + (size_t)pl * NCODE + j * 4);

    // A cp.async: 16 k-rows x 256 d
    const uint32_t a_s0 = smem_u32(Asm[0]), a_s1 = smem_u32(Asm[1]);
    #pragma unroll
    for (int i = 0; i < 4; i++) {
        int idx = tid + i * 256, row = idx >> 6, col = (idx & 63) * 4;
        cpa16(a_s0 + (row * SA + col) * 4, g_cbR + row * DDIM + col);
    }
    asm volatile("cp.async.commit_group;" ::: "memory");

    float acc[4][4][4] = {};

    for (int c = 0; c < 64; c++) {
        const int buf = c & 1;
        asm volatile("cp.async.wait_group 0;" ::: "memory");

        float* bs = Bsm[buf];
        bs[(j * 4 + 0) * SB + pl] = br.x;
        bs[(j * 4 + 1) * SB + pl] = br.y;
        bs[(j * 4 + 2) * SB + pl] = br.z;
        bs[(j * 4 + 3) * SB + pl] = br.w;
        __syncthreads();

        if (c < 63) {
            const float* abase = g_cbR + (size_t)(c + 1) * 16 * DDIM;
            uint32_t adst = buf ? a_s0 : a_s1;
            #pragma unroll
            for (int i = 0; i < 4; i++) {
                int idx = tid + i * 256, row = idx >> 6, col = (idx & 63) * 4;
                cpa16(adst + (row * SA + col) * 4, abase + row * DDIM + col);
            }
            asm volatile("cp.async.commit_group;" ::: "memory");
            br = *(const float4*)(spl + (size_t)pl * NCODE + (c + 1) * 16 + j * 4);
        }

        const float* as = Asm[buf];
        #pragma unroll
        for (int kk = 0; kk < 16; kk += 8) {
            uint32_t afr[4][4], bfr[4][2];
            #pragma unroll
            for (int mf = 0; mf < 4; mf++) {
                int mm = wm * 64 + mf * 16 + gid;
                afr[mf][0] = __float_as_uint(as[(kk + tig) * SA + mm]);
                afr[mf][1] = __float_as_uint(as[(kk + tig) * SA + mm + 8]);
                afr[mf][2] = __float_as_uint(as[(kk + 4 + tig) * SA + mm]);
                afr[mf][3] = __float_as_uint(as[(kk + 4 + tig) * SA + mm + 8]);
            }
            #pragma unroll
            for (int nf = 0; nf < 4; nf++) {
                int nn = wn * 32 + nf * 8 + gid;
                bfr[nf][0] = __float_as_uint(bs[(kk + tig) * SB + nn]);
                bfr[nf][1] = __float_as_uint(bs[(kk + 4 + tig) * SB + nn]);
            }
            #pragma unroll
            for (int mf = 0; mf < 4; mf++)
                #pragma unroll
                for (int nf = 0; nf < 4; nf++)
                    mma_tf32(acc[mf][nf], afr[mf], bfr[nf]);
        }
        __syncthreads();
    }

    const int bimg = p0 >> 10, hwb = p0 & 1023;
    #pragma unroll
    for (int mf = 0; mf < 4; mf++) {
        const int d = wm * 64 + mf * 16 + gid;
        float* orow = out + (size_t)bimg * (DDIM * 1024) + (size_t)d * 1024 + hwb;
        #pragma unroll
        for (int nf = 0; nf < 4; nf++) {
            const int col = wn * 32 + nf * 8 + 2 * tig;
            *(float2*)&orow[col]            = make_float2(acc[mf][nf][0], acc[mf][nf][1]);
            *(float2*)&orow[col + 8 * 1024] = make_float2(acc[mf][nf][2], acc[mf][nf][3]);
        }
    }
}

// ---------------------------------------------------------------- finalize
__global__ void finalize_kernel(float* __restrict__ out) {
    __shared__ float red[32];
    int t = threadIdx.x;   // 1024 threads
    float v = g_avg[t] * (1.f / 16384.f);
    float hterm = v * __logf(v + 1e-10f);
    #pragma unroll
    for (int o = 16; o; o >>= 1) hterm += __shfl_xor_sync(0xffffffffu, hterm, o);
    if ((t & 31) == 0) red[t >> 5] = hterm;
    __syncthreads();
    if (t < 32) {
        float s = red[t];
        #pragma unroll
        for (int o = 16; o; o >>= 1) s += __shfl_xor_sync(0xffffffffu, s, o);
        if (t == 0) {
            out[PERP_OFF] = __expf(-s);
            out[KL_OFF] = (1e-3f / 16384.f) * g_kl;
        }
    }
}

// ---------------------------------------------------------------- launch
extern "C" void kernel_launch(void* const* d_in, const int* in_sizes, int n_in,
                              void* d_out, int out_size) {
    const float* logits = (const float*)d_in[0];
    const float* cb     = (const float*)d_in[1];
    const float* noise  = (const float*)d_in[2];
    float* out = (float*)d_out;

    const int px_smem = 16 * PXS * 4;
    cudaFuncSetAttribute(pixel_kernel,
                         cudaFuncAttributeMaxDynamicSharedMemorySize, px_smem);
    cudaFuncSetAttribute(gemm_mma,
                         cudaFuncAttributeMaxDynamicSharedMemorySize, GEMM_SMEM);

    init_kernel<<<1, 1024>>>();
    round_cb<<<256, 1024>>>(cb);
    pixel_kernel<<<1024, 512, px_smem>>>(logits, noise, out);
    avg_kernel<<<128, 256>>>();
    gemm_mma<<<NPIX / 64, 256, GEMM_SMEM>>>(out);
    finalize_kernel<<<1, 1024>>>(out);
}

// round 6
// speedup vs baseline: 3.6891x; 1.3704x over previous
#include <cuda_runtime.h>
#include <cuda_fp16.h>
#include <cstdint>

// Problem constants
#define NPIX   16384            // B*H*W
#define NCODE  1024             // N (= K of the GEMM)
#define DDIM   256              // D (= M of the GEMM)
#define ZQ_SIZE 4194304         // B*D*H*W
#define KL_OFF  ZQ_SIZE
#define IDX_OFF (ZQ_SIZE + 1)
#define PERP_OFF (ZQ_SIZE + 1 + NPIX)

// Static device scratch (no allocation allowed)
__device__ __half g_sampleH[(size_t)NPIX * NCODE];  // 32 MB, [pixel][k]
__device__ __half g_cbH[(size_t)DDIM * NCODE];      // 512 KB, [d][k] (transposed)
__device__ float g_avg[NCODE];
__device__ float g_kl;

// ---------------------------------------------------------------- helpers
__device__ __forceinline__ uint32_t smem_u32(const void* p) {
    uint32_t a;
    asm("{ .reg .u64 t; cvta.to.shared.u64 t, %1; cvt.u32.u64 %0, t; }" : "=r"(a) : "l"(p));
    return a;
}
__device__ __forceinline__ void cpa16(uint32_t d, const void* s) {
    asm volatile("cp.async.cg.shared.global [%0], [%1], 16;" :: "r"(d), "l"(s));
}
__device__ __forceinline__ void mma_f16(float* c, const uint32_t* a, const uint32_t* b) {
    asm volatile(
        "mma.sync.aligned.m16n8k16.row.col.f32.f16.f16.f32 "
        "{%0,%1,%2,%3}, {%4,%5,%6,%7}, {%8,%9}, {%0,%1,%2,%3};"
        : "+f"(c[0]), "+f"(c[1]), "+f"(c[2]), "+f"(c[3])
        : "r"(a[0]), "r"(a[1]), "r"(a[2]), "r"(a[3]), "r"(b[0]), "r"(b[1]));
}

// Branch-free fused lgamma + digamma for x >= 1 (double shift + Stirling at x+2).
__device__ __forceinline__ void lgamma_digamma(float x, float& lg, float& ps) {
    float prod = x * (x + 1.f);
    float invp = __fdividef(1.f, prod);
    float x2   = x + 2.f;
    float lx   = __logf(x2);
    float inv  = __fdividef(1.f, x2);
    float inv2 = inv * inv;
    lg = (x2 - 0.5f) * lx - x2 + 0.9189385332046727f
       + inv * (0.083333333333f - inv2 * (2.7777777778e-3f - inv2 * 7.9365079365e-4f))
       - __logf(prod);
    ps = lx - 0.5f * inv
       - inv2 * (0.083333333333f - inv2 * (8.3333333333e-3f - inv2 * 3.9682539683e-3f))
       - (2.f * x + 1.f) * invp;
}

// ---------------------------------------------------------------- init
__global__ void init_kernel() {
    int t = threadIdx.x;
    if (t < NCODE) g_avg[t] = 0.f;
    if (t == 0) g_kl = 0.f;
}

// codebook: transpose [n][d] -> [d][n] and convert to fp16
__global__ __launch_bounds__(256) void transpose_cb(const float* __restrict__ cb) {
    __shared__ float t[32][33];
    int n0 = blockIdx.x * 32, d0 = blockIdx.y * 32;
    int x = threadIdx.x & 31, y = threadIdx.x >> 5;  // y in 0..7
    #pragma unroll
    for (int j = 0; j < 4; j++)
        t[y + j * 8][x] = cb[(size_t)(n0 + y + j * 8) * DDIM + d0 + x];
    __syncthreads();
    #pragma unroll
    for (int j = 0; j < 4; j++)
        g_cbH[(size_t)(d0 + y + j * 8) * NCODE + n0 + x] = __float2half_rn(t[x][y + j * 8]);
}

// ---------------------------------------------------------------- per-pixel pass
// 1024 blocks x 512 threads. Block = 16 pixels. smem 65.6KB -> 2 CTAs/SM.
// t = alpha/(-log u); softmax(T=0.5) == t^2 / sum t^2; argmax(t) == argmax.
#define PXS 1025
extern __shared__ float smem_dyn[];
__global__ __launch_bounds__(512) void pixel_kernel(
    const float* __restrict__ logits,
    const float* __restrict__ noise,
    float* __restrict__ out)
{
    float* alpha_t = smem_dyn;              // [16][PXS]
    const int tid = threadIdx.x;
    const int blk = blockIdx.x;             // b*64 + h*2 + half
    const int b = blk >> 6, h = (blk >> 1) & 31, half = blk & 1;
    const int w0 = half * 16;

    // Stage: softplus(logits)+1, transposed to [w][n]
    const float* lg = logits + (size_t)b * (NCODE * 1024) + (size_t)h * 32 + w0;
    #pragma unroll 4
    for (int i = tid; i < 16 * NCODE; i += 512) {
        int n = i >> 4, w = i & 15;
        float x = lg[(size_t)n * 1024 + w];
        float e = __expf(-fabsf(x));
        float sp = fmaxf(x, 0.f) + __logf(1.f + e);
        alpha_t[w * PXS + n] = sp + 1.f;
    }
    __syncthreads();

    const int warp = tid >> 5, lane = tid & 31;      // warp = pixel-in-block
    const int p = b * 1024 + h * 32 + w0 + warp;     // global pixel index
    float* row = alpha_t + warp * PXS;
    const float* nz = noise + (size_t)p * NCODE;

    // Pass 1: KL sums, t = a / (-log u), Z = sum t^2, argmax t
    float S = 0.f, slg = 0.f, sdg = 0.f, Z = 0.f, m = -1.f;
    int bi = 0;
    #pragma unroll 4
    for (int k = 0; k < 32; k++) {
        int n = k * 32 + lane;
        float a = row[n];
        float lga, psa;
        lgamma_digamma(a, lga, psa);
        S += a; slg += lga; sdg += (a - 1.f) * psa;
        float L = -__logf(nz[n]);
        float t = __fdividef(a, L);
        row[n] = t;
        Z += t * t;
        if (t > m) { m = t; bi = n; }
    }
    #pragma unroll
    for (int o = 16; o; o >>= 1) {
        S   += __shfl_xor_sync(0xffffffffu, S, o);
        slg += __shfl_xor_sync(0xffffffffu, slg, o);
        sdg += __shfl_xor_sync(0xffffffffu, sdg, o);
        Z   += __shfl_xor_sync(0xffffffffu, Z, o);
        float mo = __shfl_xor_sync(0xffffffffu, m, o);
        int   bo = __shfl_xor_sync(0xffffffffu, bi, o);
        if (mo > m || (mo == m && bo < bi)) { m = mo; bi = bo; }
    }
    float invZ = __fdividef(1.f, Z);

    // Pass 2: normalized sample -> fp16 global + fp32 smem (for column sums)
    __half* srow = g_sampleH + (size_t)p * NCODE;
    #pragma unroll 4
    for (int k = 0; k < 32; k++) {
        int n = k * 32 + lane;
        float t = row[n];
        float s = t * t * invZ;
        row[n] = s;
        srow[n] = __float2half_rn(s);
    }

    if (lane == 0) {
        float lgS, psS, lgN, psN;
        lgamma_digamma(S, lgS, psS);
        lgamma_digamma(1024.f, lgN, psN);
        float kl = lgS - slg - lgN + sdg - (S - 1024.f) * psS;
        atomicAdd(&g_kl, kl);
        out[IDX_OFF + p] = (float)bi;
    }
    __syncthreads();

    // Column sums over the 16 pixels -> one atomic per code per block
    #pragma unroll
    for (int c = tid; c < NCODE; c += 512) {
        float acc = 0.f;
        #pragma unroll
        for (int w = 0; w < 16; w++) acc += alpha_t[w * PXS + c];
        atomicAdd(&g_avg[c], acc);
    }
}

// ---------------------------------------------------------------- fp16 mma.sync GEMM
// C[d=256][p=64-tile] = sum_k cbT[d][k] * sample[p][k]
// 256 threads (8 warps), warp tile 64x32 (wm=warp&3, wn=warp>>2), K-tile 16.
// Both smem tiles [row][k] with 48B row stride (12 words): gid*12+tig hits all
// 32 banks -> conflict-free 4B fragment loads.
#define RSH 24   // halfs per row (48 bytes)
#define GEMM_SMEM ((2 * 256 * RSH + 2 * 64 * RSH) * 2)   // 30720 B

__global__ __launch_bounds__(256, 2) void gemm_mma(float* __restrict__ out) {
    extern __shared__ __half hsm[];
    __half* Asm[2] = { hsm, hsm + 256 * RSH };
    __half* Bsm[2] = { hsm + 512 * RSH, hsm + 512 * RSH + 64 * RSH };

    const int tid = threadIdx.x, warp = tid >> 5, lane = tid & 31;
    const int gid = lane >> 2, tig = lane & 3;
    const int wm = warp & 3, wn = warp >> 2;       // m-offset 64*wm, n-offset 32*wn
    const int p0 = blockIdx.x * 64;

    const __half* spl = g_sampleH + (size_t)p0 * NCODE;

    const uint32_t a_s[2] = { smem_u32(Asm[0]), smem_u32(Asm[1]) };
    const uint32_t b_s[2] = { smem_u32(Bsm[0]), smem_u32(Bsm[1]) };

    // Issue tile 0: A = 512 16B-chunks (256 rows x 2), B = 128 chunks (64 x 2)
    {
        const int row = tid >> 1, hh = tid & 1;
        cpa16(a_s[0] + row * 48 + hh * 16, g_cbH + (size_t)row * NCODE + hh * 8);
        const int row2 = (tid + 256) >> 1, h2 = tid & 1;
        cpa16(a_s[0] + row2 * 48 + h2 * 16, g_cbH + (size_t)row2 * NCODE + h2 * 8);
        if (tid < 128)
            cpa16(b_s[0] + row * 48 + hh * 16, spl + (size_t)row * NCODE + hh * 8);
    }
    asm volatile("cp.async.commit_group;" ::: "memory");

    float acc[4][4][4] = {};

    for (int c = 0; c < 64; c++) {
        const int buf = c & 1;
        asm volatile("cp.async.wait_group 0;" ::: "memory");
        __syncthreads();

        if (c < 63) {
            const int k0 = (c + 1) * 16;
            const int row = tid >> 1, hh = tid & 1;
            cpa16(a_s[buf ^ 1] + row * 48 + hh * 16,
                  g_cbH + (size_t)row * NCODE + k0 + hh * 8);
            const int row2 = (tid + 256) >> 1;
            cpa16(a_s[buf ^ 1] + row2 * 48 + hh * 16,
                  g_cbH + (size_t)row2 * NCODE + k0 + hh * 8);
            if (tid < 128)
                cpa16(b_s[buf ^ 1] + row * 48 + hh * 16,
                      spl + (size_t)row * NCODE + k0 + hh * 8);
            asm volatile("cp.async.commit_group;" ::: "memory");
        }

        const uint32_t as = a_s[buf], bs = b_s[buf];
        uint32_t afr[4][4], bfr[4][2];
        #pragma unroll
        for (int mf = 0; mf < 4; mf++) {
            const uint32_t base = as + (wm * 64 + mf * 16 + gid) * 48 + tig * 4;
            asm volatile("ld.shared.b32 %0, [%1];"      : "=r"(afr[mf][0]) : "r"(base));
            asm volatile("ld.shared.b32 %0, [%1+384];"  : "=r"(afr[mf][1]) : "r"(base));
            asm volatile("ld.shared.b32 %0, [%1+16];"   : "=r"(afr[mf][2]) : "r"(base));
            asm volatile("ld.shared.b32 %0, [%1+400];"  : "=r"(afr[mf][3]) : "r"(base));
        }
        #pragma unroll
        for (int nf = 0; nf < 4; nf++) {
            const uint32_t base = bs + (wn * 32 + nf * 8 + gid) * 48 + tig * 4;
            asm volatile("ld.shared.b32 %0, [%1];"    : "=r"(bfr[nf][0]) : "r"(base));
            asm volatile("ld.shared.b32 %0, [%1+16];" : "=r"(bfr[nf][1]) : "r"(base));
        }
        #pragma unroll
        for (int mf = 0; mf < 4; mf++)
            #pragma unroll
            for (int nf = 0; nf < 4; nf++)
                mma_f16(acc[mf][nf], afr[mf], bfr[nf]);
        __syncthreads();
    }

    const int bimg = p0 >> 10, hwb = p0 & 1023;
    #pragma unroll
    for (int mf = 0; mf < 4; mf++) {
        const int d = wm * 64 + mf * 16 + gid;
        float* orow = out + (size_t)bimg * (DDIM * 1024) + (size_t)d * 1024 + hwb;
        #pragma unroll
        for (int nf = 0; nf < 4; nf++) {
            const int col = wn * 32 + nf * 8 + 2 * tig;
            *(float2*)&orow[col]            = make_float2(acc[mf][nf][0], acc[mf][nf][1]);
            *(float2*)&orow[col + 8 * 1024] = make_float2(acc[mf][nf][2], acc[mf][nf][3]);
        }
    }
}

// ---------------------------------------------------------------- finalize
__global__ void finalize_kernel(float* __restrict__ out) {
    __shared__ float red[32];
    int t = threadIdx.x;   // 1024 threads
    float v = g_avg[t] * (1.f / 16384.f);
    float hterm = v * __logf(v + 1e-10f);
    #pragma unroll
    for (int o = 16; o; o >>= 1) hterm += __shfl_xor_sync(0xffffffffu, hterm, o);
    if ((t & 31) == 0) red[t >> 5] = hterm;
    __syncthreads();
    if (t < 32) {
        float s = red[t];
        #pragma unroll
        for (int o = 16; o; o >>= 1) s += __shfl_xor_sync(0xffffffffu, s, o);
        if (t == 0) {
            out[PERP_OFF] = __expf(-s);
            out[KL_OFF] = (1e-3f / 16384.f) * g_kl;
        }
    }
}

// ---------------------------------------------------------------- launch
extern "C" void kernel_launch(void* const* d_in, const int* in_sizes, int n_in,
                              void* d_out, int out_size) {
    const float* logits = (const float*)d_in[0];
    const float* cb     = (const float*)d_in[1];
    const float* noise  = (const float*)d_in[2];
    float* out = (float*)d_out;

    const int px_smem = 16 * PXS * 4;
    cudaFuncSetAttribute(pixel_kernel,
                         cudaFuncAttributeMaxDynamicSharedMemorySize, px_smem);

    init_kernel<<<1, 1024>>>();
    transpose_cb<<<dim3(32, 8), 256>>>(cb);
    pixel_kernel<<<1024, 512, px_smem>>>(logits, noise, out);
    gemm_mma<<<NPIX / 64, 256, GEMM_SMEM>>>(out);
    finalize_kernel<<<1, 1024>>>(out);
}

// round 7
// speedup vs baseline: 4.9809x; 1.3502x over previous
#include <cuda_runtime.h>
#include <cuda_fp16.h>
#include <cstdint>

// Problem constants
#define NPIX   16384            // B*H*W
#define NCODE  1024             // N (= K of the GEMM)
#define DDIM   256              // D (= M of the GEMM)
#define ZQ_SIZE 4194304         // B*D*H*W
#define KL_OFF  ZQ_SIZE
#define IDX_OFF (ZQ_SIZE + 1)
#define PERP_OFF (ZQ_SIZE + 1 + NPIX)

// Static device scratch (no allocation allowed)
__device__ __half g_sampleH[(size_t)NPIX * NCODE];  // 32 MB, [pixel][k]
__device__ __half g_cbH[(size_t)DDIM * NCODE];      // 512 KB, [d][k] (transposed)
__device__ float g_avg[NCODE];
__device__ float g_kl;

// ---------------------------------------------------------------- helpers
__device__ __forceinline__ uint32_t smem_u32(const void* p) {
    uint32_t a;
    asm("{ .reg .u64 t; cvta.to.shared.u64 t, %1; cvt.u32.u64 %0, t; }" : "=r"(a) : "l"(p));
    return a;
}
__device__ __forceinline__ void cpa16(uint32_t d, const void* s) {
    asm volatile("cp.async.cg.shared.global [%0], [%1], 16;" :: "r"(d), "l"(s));
}
__device__ __forceinline__ void ldsm4(uint32_t* r, uint32_t a) {
    asm volatile("ldmatrix.sync.aligned.m8n8.x4.shared.b16 {%0,%1,%2,%3}, [%4];"
                 : "=r"(r[0]), "=r"(r[1]), "=r"(r[2]), "=r"(r[3]) : "r"(a));
}
__device__ __forceinline__ void mma_f16(float* c, const uint32_t* a, const uint32_t* b) {
    asm volatile(
        "mma.sync.aligned.m16n8k16.row.col.f32.f16.f16.f32 "
        "{%0,%1,%2,%3}, {%4,%5,%6,%7}, {%8,%9}, {%0,%1,%2,%3};"
        : "+f"(c[0]), "+f"(c[1]), "+f"(c[2]), "+f"(c[3])
        : "r"(a[0]), "r"(a[1]), "r"(a[2]), "r"(a[3]), "r"(b[0]), "r"(b[1]));
}

// Branch-free fused lgamma + digamma for x >= 1 (double shift + Stirling at x+2).
// Single MUFU reciprocal: 1/(x(x+1)(x+2)) recovered into both needed inverses.
__device__ __forceinline__ void lgamma_digamma(float x, float& lg, float& ps) {
    float prod = x * (x + 1.f);
    float x2   = x + 2.f;
    float invall = __fdividef(1.f, prod * x2);
    float inv  = invall * prod;      // 1/(x+2)
    float invp = invall * x2;        // 1/(x(x+1))
    float lx   = __logf(x2);
    float inv2 = inv * inv;
    lg = (x2 - 0.5f) * lx - x2 + 0.9189385332046727f
       + inv * (0.083333333333f - inv2 * (2.7777777778e-3f - inv2 * 7.9365079365e-4f))
       - __logf(prod);
    ps = lx - 0.5f * inv
       - inv2 * (0.083333333333f - inv2 * (8.3333333333e-3f - inv2 * 3.9682539683e-3f))
       - (2.f * x + 1.f) * invp;
}

// ---------------------------------------------------------------- codebook transpose + init
// transpose [n][d] -> [d][n], fp16; block (0,0) also zeroes the reduction scratch.
__global__ __launch_bounds__(256) void transpose_cb(const float* __restrict__ cb) {
    __shared__ float t[32][33];
    if (blockIdx.x == 0 && blockIdx.y == 0) {
        int n = threadIdx.x * 4;
        *(float4*)&g_avg[n] = make_float4(0.f, 0.f, 0.f, 0.f);
        if (threadIdx.x == 0) g_kl = 0.f;
    }
    int n0 = blockIdx.x * 32, d0 = blockIdx.y * 32;
    int x = threadIdx.x & 31, y = threadIdx.x >> 5;  // y in 0..7
    #pragma unroll
    for (int j = 0; j < 4; j++)
        t[y + j * 8][x] = cb[(size_t)(n0 + y + j * 8) * DDIM + d0 + x];
    __syncthreads();
    #pragma unroll
    for (int j = 0; j < 4; j++)
        g_cbH[(size_t)(d0 + y + j * 8) * NCODE + n0 + x] = __float2half_rn(t[x][y + j * 8]);
}

// ---------------------------------------------------------------- per-pixel pass
// 1024 blocks x 512 threads. Block = 16 pixels.
// t = alpha/(-log u); softmax(T=0.5) == t^2 / sum t^2; argmax(t) == argmax.
#define PXS 1025
extern __shared__ float smem_dyn[];
__global__ __launch_bounds__(512) void pixel_kernel(
    const float* __restrict__ logits,
    const float* __restrict__ noise,
    float* __restrict__ out)
{
    float* alpha_t = smem_dyn;              // [16][PXS]
    const int tid = threadIdx.x;
    const int blk = blockIdx.x;             // b*64 + h*2 + half
    const int b = blk >> 6, h = (blk >> 1) & 31, half = blk & 1;
    const int w0 = half * 16;

    // Stage: softplus(logits)+1, transposed to [w][n]
    const float* lg = logits + (size_t)b * (NCODE * 1024) + (size_t)h * 32 + w0;
    #pragma unroll 4
    for (int i = tid; i < 16 * NCODE; i += 512) {
        int n = i >> 4, w = i & 15;
        float x = lg[(size_t)n * 1024 + w];
        float e = __expf(-fabsf(x));
        float sp = fmaxf(x, 0.f) + __logf(1.f + e);
        alpha_t[w * PXS + n] = sp + 1.f;
    }
    __syncthreads();

    const int warp = tid >> 5, lane = tid & 31;      // warp = pixel-in-block
    const int p = b * 1024 + h * 32 + w0 + warp;     // global pixel index
    float* row = alpha_t + warp * PXS;
    const float* nz = noise + (size_t)p * NCODE;

    // Pass 1: KL sums, t = a / (-log u), Z = sum t^2, argmax t
    float S = 0.f, slg = 0.f, sdg = 0.f, Z = 0.f, m = -1.f;
    int bi = 0;
    #pragma unroll 4
    for (int k = 0; k < 32; k++) {
        int n = k * 32 + lane;
        float a = row[n];
        float lga, psa;
        lgamma_digamma(a, lga, psa);
        S += a; slg += lga; sdg += (a - 1.f) * psa;
        float L = -__logf(nz[n]);
        float t = __fdividef(a, L);
        row[n] = t;
        Z += t * t;
        if (t > m) { m = t; bi = n; }
    }
    #pragma unroll
    for (int o = 16; o; o >>= 1) {
        S   += __shfl_xor_sync(0xffffffffu, S, o);
        slg += __shfl_xor_sync(0xffffffffu, slg, o);
        sdg += __shfl_xor_sync(0xffffffffu, sdg, o);
        Z   += __shfl_xor_sync(0xffffffffu, Z, o);
        float mo = __shfl_xor_sync(0xffffffffu, m, o);
        int   bo = __shfl_xor_sync(0xffffffffu, bi, o);
        if (mo > m || (mo == m && bo < bi)) { m = mo; bi = bo; }
    }
    float invZ = __fdividef(1.f, Z);

    // Pass 2: normalized sample -> fp16 global + fp32 smem (for column sums)
    __half* srow = g_sampleH + (size_t)p * NCODE;
    #pragma unroll 4
    for (int k = 0; k < 32; k++) {
        int n = k * 32 + lane;
        float t = row[n];
        float s = t * t * invZ;
        row[n] = s;
        srow[n] = __float2half_rn(s);
    }

    if (lane == 0) {
        float lgS, psS, lgN, psN;
        lgamma_digamma(S, lgS, psS);
        lgamma_digamma(1024.f, lgN, psN);
        float kl = lgS - slg - lgN + sdg - (S - 1024.f) * psS;
        atomicAdd(&g_kl, kl);
        out[IDX_OFF + p] = (float)bi;
    }
    __syncthreads();

    // Column sums over the 16 pixels -> one atomic per code per block
    #pragma unroll
    for (int c = tid; c < NCODE; c += 512) {
        float acc = 0.f;
        #pragma unroll
        for (int w = 0; w < 16; w++) acc += alpha_t[w * PXS + c];
        atomicAdd(&g_avg[c], acc);
    }
}

// ---------------------------------------------------------------- fp16 mma GEMM
// C[d-tile 128][p-tile 128] = sum_k cbT[d][k] * sample[p][k]
// 8 warps: wm=warp>>2 (x64), wn=warp&3 (x32). K-tile 32, 3-stage cp.async.
// Row stride 80B: 20r mod 32 covers all banks -> conflict-free ldmatrix.
#define KT        32
#define ROWB      80                       // bytes per smem row
#define STG_BYTES (128 * ROWB)             // 10240 per operand per stage
#define GEMM_SMEM (6 * STG_BYTES)          // 61440

__device__ __forceinline__ void gemm_issue(uint32_t Ab, uint32_t Bb,
                                           const __half* arow, const __half* brow,
                                           int k0, int tid) {
    const int row = tid >> 1, c0 = (tid & 1) * 2;     // 2 chunks each of A,B
    #pragma unroll
    for (int j = 0; j < 2; j++) {
        cpa16(Ab + row * ROWB + (c0 + j) * 16, arow + (size_t)row * NCODE + k0 + (c0 + j) * 8);
        cpa16(Bb + row * ROWB + (c0 + j) * 16, brow + (size_t)row * NCODE + k0 + (c0 + j) * 8);
    }
    asm volatile("cp.async.commit_group;" ::: "memory");
}

__global__ __launch_bounds__(256, 2) void gemm_mma(float* __restrict__ out) {
    extern __shared__ __align__(16) char gsm[];
    const uint32_t base = smem_u32(gsm);

    const int tid = threadIdx.x, warp = tid >> 5, lane = tid & 31;
    const int gid = lane >> 2, tig = lane & 3;
    const int wm = warp >> 2, wn = warp & 3;
    const int p0 = blockIdx.x * 128, d0 = blockIdx.y * 128;

    const __half* arow = g_cbH + (size_t)d0 * NCODE;
    const __half* brow = g_sampleH + (size_t)p0 * NCODE;

    // lane-fixed ldmatrix address components
    const uint32_t a_lrow = (uint32_t)(wm * 64 + (lane & 15)) * ROWB + ((lane >> 4) & 1) * 16;
    const uint32_t b_lrow = (uint32_t)(wn * 32 + ((lane >> 4) & 1) * 8 + (lane & 7)) * ROWB
                          + ((lane >> 3) & 1) * 16;

    gemm_issue(base, base + 3 * STG_BYTES, arow, brow, 0, tid);
    gemm_issue(base + STG_BYTES, base + 4 * STG_BYTES, arow, brow, KT, tid);

    float acc[4][4][4] = {};

    for (int c = 0; c < 32; c++) {
        const int buf = c % 3;
        if (c < 30) asm volatile("cp.async.wait_group 1;" ::: "memory");
        else        asm volatile("cp.async.wait_group 0;" ::: "memory");
        __syncthreads();
        if (c + 2 < 32) {
            const int nb = (c + 2) % 3;
            gemm_issue(base + nb * STG_BYTES, base + (3 + nb) * STG_BYTES,
                       arow, brow, (c + 2) * KT, tid);
        }

        const uint32_t Ab = base + buf * STG_BYTES + a_lrow;
        const uint32_t Bb = base + (3 + buf) * STG_BYTES + b_lrow;
        #pragma unroll
        for (int sk = 0; sk < 2; sk++) {
            const uint32_t ko = sk * 32;
            uint32_t afr[4][4], bfr[4][2];
            #pragma unroll
            for (int mf = 0; mf < 4; mf++)
                ldsm4(afr[mf], Ab + mf * (16 * ROWB) + ko);
            #pragma unroll
            for (int np = 0; np < 2; np++) {
                uint32_t r[4];
                ldsm4(r, Bb + np * (16 * ROWB) + ko);
                bfr[2 * np][0] = r[0]; bfr[2 * np][1] = r[1];
                bfr[2 * np + 1][0] = r[2]; bfr[2 * np + 1][1] = r[3];
            }
            #pragma unroll
            for (int mf = 0; mf < 4; mf++)
                #pragma unroll
                for (int nf = 0; nf < 4; nf++)
                    mma_f16(acc[mf][nf], afr[mf], bfr[nf]);
        }
        __syncthreads();
    }

    const int bimg = p0 >> 10, hwb = p0 & 1023;
    #pragma unroll
    for (int mf = 0; mf < 4; mf++) {
        const int d = d0 + wm * 64 + mf * 16 + gid;
        float* orow = out + (size_t)bimg * (DDIM * 1024) + (size_t)d * 1024 + hwb;
        #pragma unroll
        for (int nf = 0; nf < 4; nf++) {
            const int col = wn * 32 + nf * 8 + 2 * tig;
            *(float2*)&orow[col]            = make_float2(acc[mf][nf][0], acc[mf][nf][1]);
            *(float2*)&orow[col + 8 * 1024] = make_float2(acc[mf][nf][2], acc[mf][nf][3]);
        }
    }
}

// ---------------------------------------------------------------- finalize
__global__ void finalize_kernel(float* __restrict__ out) {
    __shared__ float red[32];
    int t = threadIdx.x;   // 1024 threads
    float v = g_avg[t] * (1.f / 16384.f);
    float hterm = v * __logf(v + 1e-10f);
    #pragma unroll
    for (int o = 16; o; o >>= 1) hterm += __shfl_xor_sync(0xffffffffu, hterm, o);
    if ((t & 31) == 0) red[t >> 5] = hterm;
    __syncthreads();
    if (t < 32) {
        float s = red[t];
        #pragma unroll
        for (int o = 16; o; o >>= 1) s += __shfl_xor_sync(0xffffffffu, s, o);
        if (t == 0) {
            out[PERP_OFF] = __expf(-s);
            out[KL_OFF] = (1e-3f / 16384.f) * g_kl;
        }
    }
}

// ---------------------------------------------------------------- launch
extern "C" void kernel_launch(void* const* d_in, const int* in_sizes, int n_in,
                              void* d_out, int out_size) {
    const float* logits = (const float*)d_in[0];
    const float* cb     = (const float*)d_in[1];
    const float* noise  = (const float*)d_in[2];
    float* out = (float*)d_out;

    const int px_smem = 16 * PXS * 4;
    cudaFuncSetAttribute(pixel_kernel,
                         cudaFuncAttributeMaxDynamicSharedMemorySize, px_smem);
    cudaFuncSetAttribute(gemm_mma,
                         cudaFuncAttributeMaxDynamicSharedMemorySize, GEMM_SMEM);

    transpose_cb<<<dim3(32, 8), 256>>>(cb);
    pixel_kernel<<<1024, 512, px_smem>>>(logits, noise, out);
    gemm_mma<<<dim3(NPIX / 128, DDIM / 128), 256, GEMM_SMEM>>>(out);
    finalize_kernel<<<1, 1024>>>(out);
}